// round 2
// baseline (speedup 1.0000x reference)
#include <cuda_runtime.h>
#include <cuda_bf16.h>
#include <cstdint>

typedef unsigned long long ull;

// ---------------- device-global scratch (no runtime alloc allowed) -------------
__device__ float4 g_wdupE[4 * 64 * 128];   // [gate][kk][n] : {w_k,w_k,w_k1,w_k1}
__device__ float4 g_wdupD[4 * 64 * 128];
__device__ ull    g_abE[128 * 4 * 3];      // per n, per gate: {bias,bias},{a0,a0},{a1,a1}
__device__ ull    g_abD[128 * 4 * 3];
__device__ float  g_Wm1T[128 * 256];       // [k][mc]
__device__ float  g_Wm2T[256 * 112];       // [k][mc]

// ---------------- f32x2 helpers ------------------------------------------------
__device__ __forceinline__ ull f2fma(ull a, ull b, ull c) {
    ull d;
    asm("fma.rn.f32x2 %0, %1, %2, %3;" : "=l"(d) : "l"(a), "l"(b), "l"(c));
    return d;
}
__device__ __forceinline__ ull pk(float lo, float hi) {
    ull r;
    asm("mov.b64 %0, {%1, %2};" : "=l"(r) : "f"(lo), "f"(hi));
    return r;
}
__device__ __forceinline__ float2 unpk(ull v) {
    float2 r;
    asm("mov.b64 {%0, %1}, %2;" : "=f"(r.x), "=f"(r.y) : "l"(v));
    return r;
}
__device__ __forceinline__ float sigmf_(float x) {
    return __fdividef(1.0f, 1.0f + __expf(-x));
}
__device__ __forceinline__ float tanhf_(float x) {
    x = fminf(fmaxf(x, -15.0f), 15.0f);
    float e = __expf(-2.0f * x);
    return __fdividef(1.0f - e, 1.0f + e);
}

// ---------------- precompute kernels ------------------------------------------
// Fold A = Wih @ Win (512x2), bias = Wih @ bin + bg, into dup-packed layout.
__global__ void k_fold(const float* __restrict__ Wih, const float* __restrict__ Win,
                       const float* __restrict__ bin, const float* __restrict__ bg,
                       ull* __restrict__ ab_out, int E) {
    int gn = threadIdx.x;  // 512
    float a0 = 0.f, a1 = 0.f, bb = 0.f;
    for (int e = 0; e < E; e++) {
        float w = Wih[gn * E + e];
        a0 += w * Win[e * 2 + 0];
        a1 += w * Win[e * 2 + 1];
        bb += w * bin[e];
    }
    bb += bg[gn];
    int n = gn & 127, g = gn >> 7;
    ab_out[(n * 4 + g) * 3 + 0] = pk(bb, bb);
    ab_out[(n * 4 + g) * 3 + 1] = pk(a0, a0);
    ab_out[(n * 4 + g) * 3 + 2] = pk(a1, a1);
}

// Build duplicated, n-coalesced Whh layout: out[g*8192 + kk*128 + n] = {w_k,w_k,w_k1,w_k1}
__global__ void k_wdup(const float* __restrict__ Whh, float4* __restrict__ out) {
    int idx = blockIdx.x * blockDim.x + threadIdx.x;
    if (idx >= 4 * 64 * 128) return;
    int n = idx & 127;
    int kk = (idx >> 7) & 63;
    int g = idx >> 13;
    float w0 = Whh[(g * 128 + n) * 128 + 2 * kk + 0];
    float w1 = Whh[(g * 128 + n) * 128 + 2 * kk + 1];
    out[idx] = make_float4(w0, w0, w1, w1);
}

// Transposes for coalesced MLP weight reads.
__global__ void k_trans(const float* __restrict__ Wm1, const float* __restrict__ Wm2) {
    int i = blockIdx.x * blockDim.x + threadIdx.x;
    int stride = gridDim.x * blockDim.x;
    for (int j = i; j < 128 * 256; j += stride) {
        int k = j >> 8, mc = j & 255;
        g_Wm1T[j] = Wm1[mc * 128 + k];
    }
    for (int j = i; j < 256 * 112; j += stride) {
        int k = j / 112, mc = j % 112;
        g_Wm2T[j] = Wm2[mc * 256 + k];
    }
}

// ---------------- main persistent kernel ---------------------------------------
// 512 threads, 64 rows (32 pairs) per block. thread: n = tid&127, slot = tid>>7.
// h, c stored pair-packed in smem: [pair][k] float2 = {row 2p, row 2p+1}.

#define NP 32
#define TMAX 64

struct SmemLayout {
    // offsets in bytes within dynamic smem
    // hbuf0: 0          (4096 float2 = 32768 B)
    // hbuf1: 32768
    // c_s  : 65536      (4096 float2)
    // ab_s : 98304      (1536 ull = 12288 B)
    // region: 110592    (65536 B)  -> offx[TMAX*32] ull, offy follows; or m1_s[32*256] float2
    // base_s: 176128    (64 float2 = 512 B)
    // offc : 176640     (128 float = 512 B)
    // wr_s : 177152     (256 float = 1024 B)
    // total 178176
};
#define SMEM_BYTES 178176

__device__ __forceinline__ void lstm_step(
    const float2* __restrict__ hin, float2* __restrict__ hout,
    float2* __restrict__ c_s, const ull* __restrict__ ab_s,
    const float4* __restrict__ wd,
    const ull* __restrict__ offx, const ull* __restrict__ offy,
    int n, int slot)
{
    ull acc[4][8];
    {
        ull bb[4], a0[4], a1[4];
#pragma unroll
        for (int g = 0; g < 4; g++) {
            const ull* q = &ab_s[(n * 4 + g) * 3];
            bb[g] = q[0]; a0[g] = q[1]; a1[g] = q[2];
        }
#pragma unroll
        for (int j = 0; j < 8; j++) {
            int p = slot * 8 + j;
            ull ox = offx[p], oy = offy[p];
#pragma unroll
            for (int g = 0; g < 4; g++)
                acc[g][j] = f2fma(a0[g], ox, f2fma(a1[g], oy, bb[g]));
        }
    }
    const float4* wp = wd + n;
    const float2* hp = hin + (size_t)slot * 8 * 128;
#pragma unroll 2
    for (int kk = 0; kk < 64; kk++) {
        ull w[4][2];
#pragma unroll
        for (int g = 0; g < 4; g++) {
            ulonglong2 lw = __ldg((const ulonglong2*)(wp + (g * 64 + kk) * 128));
            w[g][0] = lw.x; w[g][1] = lw.y;
        }
#pragma unroll
        for (int j = 0; j < 8; j++) {
            ulonglong2 hv = *(const ulonglong2*)(hp + j * 128 + 2 * kk);
#pragma unroll
            for (int g = 0; g < 4; g++) {
                acc[g][j] = f2fma(w[g][0], hv.x, acc[g][j]);
                acc[g][j] = f2fma(w[g][1], hv.y, acc[g][j]);
            }
        }
    }
    // activations + state update (each (pair,n) owned by exactly this thread)
#pragma unroll
    for (int j = 0; j < 8; j++) {
        int p = slot * 8 + j;
        float2 iv = unpk(acc[0][j]);
        float2 fv = unpk(acc[1][j]);
        float2 gv = unpk(acc[2][j]);
        float2 ov = unpk(acc[3][j]);
        float2 cv = c_s[p * 128 + n];
        float c0 = sigmf_(fv.x) * cv.x + sigmf_(iv.x) * tanhf_(gv.x);
        float c1 = sigmf_(fv.y) * cv.y + sigmf_(iv.y) * tanhf_(gv.y);
        c_s[p * 128 + n] = make_float2(c0, c1);
        hout[p * 128 + n] = make_float2(sigmf_(ov.x) * tanhf_(c0),
                                        sigmf_(ov.y) * tanhf_(c1));
    }
}

__global__ void __launch_bounds__(512, 1)
k_main(const float* __restrict__ obs, const float* __restrict__ bm1,
       const float* __restrict__ bm2, const float* __restrict__ Wr,
       const float* __restrict__ br, const float* __restrict__ z,
       float* __restrict__ out, int B, int T, int S)
{
    extern __shared__ char smem[];
    float2* hbuf0 = (float2*)smem;
    float2* hbuf1 = (float2*)(smem + 32768);
    float2* c_s   = (float2*)(smem + 65536);
    ull*    ab_s  = (ull*)(smem + 98304);
    char*   region = smem + 110592;
    ull*    offx_s = (ull*)region;
    ull*    offy_s = offx_s + TMAX * NP;
    float2* m1_s   = (float2*)region;
    float2* base_s = (float2*)(smem + 176128);
    float*  offc   = (float*)(smem + 176640);   // x[64], y[64]
    float*  wr_s   = (float*)(smem + 177152);   // 256

    const int tid = threadIdx.x;
    const int n = tid & 127;
    const int slot = tid >> 7;
    const int b0 = blockIdx.x * 64;
    if (T > TMAX) T = TMAX;

    // ---- init: zero h0/c0, load encoder folded weights, build offsets ----
    for (int i = tid; i < 4096; i += 512) {
        hbuf0[i] = make_float2(0.f, 0.f);
        c_s[i] = make_float2(0.f, 0.f);
    }
    for (int i = tid; i < 1536; i += 512) ab_s[i] = g_abE[i];
    for (int i = tid; i < 256; i += 512 - 256 >= 0 ? 512 : 512) {}  // no-op guard
    if (tid < 256) wr_s[tid] = Wr[tid];

    for (int i = tid; i < 64 * T; i += 512) {
        int r = i / T, t = i % T;
        int b = b0 + r;
        float ox = 0.f, oy = 0.f;
        float cx = 0.f, cy = 0.f;
        if (b < B) {
            cx = obs[((size_t)b * T + t) * 2 + 0];
            cy = obs[((size_t)b * T + t) * 2 + 1];
            float px = 0.f, py = 0.f;
            if (t > 0) {
                px = obs[((size_t)b * T + t - 1) * 2 + 0];
                py = obs[((size_t)b * T + t - 1) * 2 + 1];
            }
            ox = cx - px; oy = cy - py;
        }
        if (t == T - 1) base_s[r] = make_float2(cx, cy);
        ((float*)&offx_s[t * NP + (r >> 1)])[r & 1] = ox;
        ((float*)&offy_s[t * NP + (r >> 1)])[r & 1] = oy;
    }
    __syncthreads();

    float2* bufs[2] = {hbuf0, hbuf1};
    int par = 0;

    // ---- encoder ----
    for (int t = 0; t < T; t++) {
        lstm_step(bufs[par], bufs[par ^ 1], c_s, ab_s, g_wdupE,
                  &offx_s[t * NP], &offy_s[t * NP], n, slot);
        __syncthreads();
        par ^= 1;
    }

    // ---- save last offsets (decoder init input) + swap to decoder weights ----
    if (tid < NP) {
        ((ull*)offc)[tid]      = offx_s[(T - 1) * NP + tid];
        ((ull*)(offc + 64))[tid] = offy_s[(T - 1) * NP + tid];
    }
    for (int i = tid; i < 1536; i += 512) ab_s[i] = g_abD[i];
    __syncthreads();

    // ---- MLP layer 1: m1 = relu(Wm1 @ hF + bm1)  (outs n and n+128) ----
    {
        const float2* hf = bufs[par];
        ull acc1[2][8];
        float b0f = bm1[n], b1f = bm1[n + 128];
#pragma unroll
        for (int j = 0; j < 8; j++) { acc1[0][j] = pk(b0f, b0f); acc1[1][j] = pk(b1f, b1f); }
        const float2* hp = hf + (size_t)slot * 8 * 128;
        for (int kk = 0; kk < 64; kk++) {
            float wA0 = g_Wm1T[(2 * kk) * 256 + n];
            float wA1 = g_Wm1T[(2 * kk + 1) * 256 + n];
            float wB0 = g_Wm1T[(2 * kk) * 256 + n + 128];
            float wB1 = g_Wm1T[(2 * kk + 1) * 256 + n + 128];
            ull w00 = pk(wA0, wA0), w01 = pk(wA1, wA1);
            ull w10 = pk(wB0, wB0), w11 = pk(wB1, wB1);
#pragma unroll
            for (int j = 0; j < 8; j++) {
                ulonglong2 hv = *(const ulonglong2*)(hp + j * 128 + 2 * kk);
                acc1[0][j] = f2fma(w00, hv.x, acc1[0][j]);
                acc1[0][j] = f2fma(w01, hv.y, acc1[0][j]);
                acc1[1][j] = f2fma(w10, hv.x, acc1[1][j]);
                acc1[1][j] = f2fma(w11, hv.y, acc1[1][j]);
            }
        }
        __syncthreads();  // all reads of offx region & hf done before m1_s overwrite
#pragma unroll
        for (int j = 0; j < 8; j++) {
            int p = slot * 8 + j;
            float2 v0 = unpk(acc1[0][j]);
            float2 v1 = unpk(acc1[1][j]);
            m1_s[p * 256 + n]       = make_float2(fmaxf(v0.x, 0.f), fmaxf(v0.y, 0.f));
            m1_s[p * 256 + n + 128] = make_float2(fmaxf(v1.x, 0.f), fmaxf(v1.y, 0.f));
        }
    }
    __syncthreads();

    // ---- MLP layer 2 + concat(z) -> dh written into bufs[par]; reset c ----
    {
        float2* hwr = bufs[par];
        if (n < 112) {
            ull acc2[8];
            float bb2 = bm2[n];
#pragma unroll
            for (int j = 0; j < 8; j++) acc2[j] = pk(bb2, bb2);
            const float2* mp = m1_s + (size_t)slot * 8 * 256;
            for (int kk = 0; kk < 128; kk++) {
                float w0 = g_Wm2T[(2 * kk) * 112 + n];
                float w1 = g_Wm2T[(2 * kk + 1) * 112 + n];
                ull W0 = pk(w0, w0), W1 = pk(w1, w1);
#pragma unroll
                for (int j = 0; j < 8; j++) {
                    ulonglong2 mv = *(const ulonglong2*)(mp + j * 256 + 2 * kk);
                    acc2[j] = f2fma(W0, mv.x, acc2[j]);
                    acc2[j] = f2fma(W1, mv.y, acc2[j]);
                }
            }
#pragma unroll
            for (int j = 0; j < 8; j++) {
                int p = slot * 8 + j;
                float2 v = unpk(acc2[j]);
                hwr[p * 128 + n] = make_float2(fmaxf(v.x, 0.f), fmaxf(v.y, 0.f));
            }
        }
        {   // z concat: 512 threads -> (pair, zz)
            int p = tid >> 4, zz = tid & 15;
            int r0 = b0 + 2 * p, r1 = r0 + 1;
            float z0 = (r0 < B) ? z[(size_t)r0 * 16 + zz] : 0.f;
            float z1 = (r1 < B) ? z[(size_t)r1 * 16 + zz] : 0.f;
            hwr[p * 128 + 112 + zz] = make_float2(z0, z1);
        }
        for (int i = tid; i < 4096; i += 512) c_s[i] = make_float2(0.f, 0.f);
    }
    __syncthreads();

    // ---- decoder ----
    const int wwid = tid >> 5, lid = tid & 31;
    const int row_l = 4 * wwid + (lid >> 3);
    const int kb = lid & 7;
    const bool rlead = (lid & 7) == 0;
    float2 mybase = base_s[row_l];
    float2 oacc = make_float2(0.f, 0.f);
    float br0 = br[0], br1 = br[1];

    for (int s = 0; s < S; s++) {
        lstm_step(bufs[par], bufs[par ^ 1], c_s, ab_s, g_wdupD,
                  (const ull*)offc, (const ull*)(offc + 64), n, slot);
        __syncthreads();
        // readout: off = Wr @ h_new + br ; cumsum output
        const float* hv2 = (const float*)bufs[par ^ 1];
        float p0 = 0.f, p1 = 0.f;
        int bidx = (row_l >> 1) * 256 + (row_l & 1);
#pragma unroll 4
        for (int m = 0; m < 16; m++) {
            int k = kb + 8 * m;
            float hvv = hv2[bidx + 2 * k];
            p0 += wr_s[k] * hvv;
            p1 += wr_s[128 + k] * hvv;
        }
        p0 += __shfl_xor_sync(0xffffffffu, p0, 1);
        p0 += __shfl_xor_sync(0xffffffffu, p0, 2);
        p0 += __shfl_xor_sync(0xffffffffu, p0, 4);
        p1 += __shfl_xor_sync(0xffffffffu, p1, 1);
        p1 += __shfl_xor_sync(0xffffffffu, p1, 2);
        p1 += __shfl_xor_sync(0xffffffffu, p1, 4);
        if (rlead) {
            float ox = p0 + br0, oy = p1 + br1;
            oacc.x += ox; oacc.y += oy;
            offc[row_l] = ox;
            offc[64 + row_l] = oy;
            int b = b0 + row_l;
            if (b < B) {
                out[((size_t)b * S + s) * 2 + 0] = mybase.x + oacc.x;
                out[((size_t)b * S + s) * 2 + 1] = mybase.y + oacc.y;
            }
        }
        __syncthreads();
        par ^= 1;
    }
}

// ---------------- launch ------------------------------------------------------
extern "C" void kernel_launch(void* const* d_in, const int* in_sizes, int n_in,
                              void* d_out, int out_size) {
    const float* obs   = (const float*)d_in[0];
    const float* We    = (const float*)d_in[2];
    const float* be    = (const float*)d_in[3];
    const float* Wih_e = (const float*)d_in[4];
    const float* Whh_e = (const float*)d_in[5];
    const float* b_e   = (const float*)d_in[6];
    const float* Wm1   = (const float*)d_in[7];
    const float* bm1   = (const float*)d_in[8];
    const float* Wm2   = (const float*)d_in[9];
    const float* bm2   = (const float*)d_in[10];
    const float* Wd    = (const float*)d_in[11];
    const float* bd    = (const float*)d_in[12];
    const float* Wih_d = (const float*)d_in[13];
    const float* Whh_d = (const float*)d_in[14];
    const float* b_d   = (const float*)d_in[15];
    const float* Wr    = (const float*)d_in[16];
    const float* br    = (const float*)d_in[17];
    const float* z     = (const float*)d_in[18];
    float* out = (float*)d_out;

    int NZ = 16;
    int B = in_sizes[18] / NZ;
    int T = in_sizes[0] / (B * 2);
    int S = out_size / (B * 2);
    int E = in_sizes[2] / 2;

    ull *abE_p, *abD_p;
    float4 *wdE_p, *wdD_p;
    cudaGetSymbolAddress((void**)&abE_p, g_abE);
    cudaGetSymbolAddress((void**)&abD_p, g_abD);
    cudaGetSymbolAddress((void**)&wdE_p, g_wdupE);
    cudaGetSymbolAddress((void**)&wdD_p, g_wdupD);

    k_fold<<<1, 512>>>(Wih_e, We, be, b_e, abE_p, E);
    k_fold<<<1, 512>>>(Wih_d, Wd, bd, b_d, abD_p, E);
    k_wdup<<<128, 256>>>(Whh_e, wdE_p);
    k_wdup<<<128, 256>>>(Whh_d, wdD_p);
    k_trans<<<64, 256>>>(Wm1, Wm2);

    static bool attr_set = false;
    if (!attr_set) {
        cudaFuncSetAttribute(k_main, cudaFuncAttributeMaxDynamicSharedMemorySize, SMEM_BYTES);
        attr_set = true;
    }
    int grid = (B + 63) / 64;
    k_main<<<grid, 512, SMEM_BYTES>>>(obs, bm1, bm2, Wr, br, z, out, B, T, S);
}

// round 3
// speedup vs baseline: 1.1929x; 1.1929x over previous
#include <cuda_runtime.h>
#include <cuda_bf16.h>
#include <cstdint>

typedef unsigned long long ull;

// ---------------- device-global scratch (no runtime alloc allowed) -------------
__device__ float4 g_wdupE[4 * 64 * 128];   // [gate][kk][n] : {w_k,w_k,w_k1,w_k1}
__device__ float4 g_wdupD[4 * 64 * 128];
__device__ ull    g_abE[128 * 4 * 3];      // per (n,gate): {bias,bias},{a0,a0},{a1,a1}
__device__ ull    g_abD[128 * 4 * 3];
__device__ float  g_Wm1T[128 * 256];       // [k][mc]
__device__ float  g_Wm2T[256 * 112];       // [k][mc]

// ---------------- f32x2 helpers ------------------------------------------------
__device__ __forceinline__ ull f2fma(ull a, ull b, ull c) {
    ull d;
    asm("fma.rn.f32x2 %0, %1, %2, %3;" : "=l"(d) : "l"(a), "l"(b), "l"(c));
    return d;
}
__device__ __forceinline__ ull pk(float lo, float hi) {
    ull r;
    asm("mov.b64 %0, {%1, %2};" : "=l"(r) : "f"(lo), "f"(hi));
    return r;
}
__device__ __forceinline__ float2 unpk(ull v) {
    float2 r;
    asm("mov.b64 {%0, %1}, %2;" : "=f"(r.x), "=f"(r.y) : "l"(v));
    return r;
}
__device__ __forceinline__ float sigmf_(float x) {
    return __fdividef(1.0f, 1.0f + __expf(-x));
}
__device__ __forceinline__ float tanhf_(float x) {
    x = fminf(fmaxf(x, -15.0f), 15.0f);
    float e = __expf(-2.0f * x);
    return __fdividef(1.0f - e, 1.0f + e);
}

// ---------------- fused precompute kernel --------------------------------------
// One kernel so the ncu capture (-s 5 -c 1) lands on k_main.
__global__ void k_prep(const float* __restrict__ Wih_e, const float* __restrict__ We,
                       const float* __restrict__ be,   const float* __restrict__ b_e,
                       const float* __restrict__ Wih_d, const float* __restrict__ Wd,
                       const float* __restrict__ bd,   const float* __restrict__ b_d,
                       const float* __restrict__ Whh_e, const float* __restrict__ Whh_d,
                       const float* __restrict__ Wm1,  const float* __restrict__ Wm2,
                       int E)
{
    int idx0 = blockIdx.x * blockDim.x + threadIdx.x;
    int stride = gridDim.x * blockDim.x;

    // fold A = Wih @ Win (512x2), bias = Wih @ bin + bgate  (encoder + decoder)
    for (int i = idx0; i < 1024; i += stride) {
        int which = i >> 9;          // 0 = enc, 1 = dec
        int gn = i & 511;
        const float* Wih = which ? Wih_d : Wih_e;
        const float* Win = which ? Wd : We;
        const float* bin = which ? bd : be;
        const float* bg  = which ? b_d : b_e;
        ull* ab_out = which ? g_abD : g_abE;
        float a0 = 0.f, a1 = 0.f, bb = 0.f;
        for (int e = 0; e < E; e++) {
            float w = Wih[gn * E + e];
            a0 += w * Win[e * 2 + 0];
            a1 += w * Win[e * 2 + 1];
            bb += w * bin[e];
        }
        bb += bg[gn];
        int n = gn & 127, g = gn >> 7;
        ab_out[(n * 4 + g) * 3 + 0] = pk(bb, bb);
        ab_out[(n * 4 + g) * 3 + 1] = pk(a0, a0);
        ab_out[(n * 4 + g) * 3 + 2] = pk(a1, a1);
    }

    // duplicated n-coalesced Whh layout
    for (int i = idx0; i < 2 * 4 * 64 * 128; i += stride) {
        int which = i >= 32768;
        int idx = i & 32767;
        const float* Whh = which ? Whh_d : Whh_e;
        float4* out = which ? g_wdupD : g_wdupE;
        int n = idx & 127;
        int kk = (idx >> 7) & 63;
        int g = idx >> 13;
        float w0 = Whh[(g * 128 + n) * 128 + 2 * kk + 0];
        float w1 = Whh[(g * 128 + n) * 128 + 2 * kk + 1];
        out[idx] = make_float4(w0, w0, w1, w1);
    }

    // MLP weight transposes
    for (int j = idx0; j < 128 * 256; j += stride) {
        int k = j >> 8, mc = j & 255;
        g_Wm1T[j] = Wm1[mc * 128 + k];
    }
    for (int j = idx0; j < 256 * 112; j += stride) {
        int k = j / 112, mc = j % 112;
        g_Wm2T[j] = Wm2[mc * 256 + k];
    }
}

// ---------------- main persistent kernel ---------------------------------------
// 512 threads, 56 rows (28 pairs) per block. thread: n = tid&127, slot = tid>>7.
// Each slot owns 7 pairs. h, c pair-packed in smem: [pair][k] float2.

#define ROWS  56
#define NPAIR 28
#define JPT   7
#define TMAX  50

// smem layout (bytes):
//  hbuf0 : 0       28672
//  hbuf1 : 28672   28672
//  c_s   : 57344   28672
//  ab_s  : 86016   12288
//  region: 98304   57344   (offsets: TMAX*NPAIR ull x + y = 22400 | m1: 28*256 f2 = 57344)
//  base_s: 155648  512     (56 float2)
//  offc  : 156160  512     (x[56], y[56] floats)
//  wr_s  : 156672  1024
#define SMEM_BYTES 157696

__device__ __forceinline__ void lstm_step(
    const float2* __restrict__ hin, float2* __restrict__ hout,
    float2* __restrict__ c_s, const ull* __restrict__ ab_s,
    const float4* __restrict__ wd,
    const ull* __restrict__ offx, const ull* __restrict__ offy,
    int n, int slot)
{
    ull acc[4][JPT];
    {
        ull bb[4], a0[4], a1[4];
#pragma unroll
        for (int g = 0; g < 4; g++) {
            const ull* q = &ab_s[(n * 4 + g) * 3];
            bb[g] = q[0]; a0[g] = q[1]; a1[g] = q[2];
        }
#pragma unroll
        for (int j = 0; j < JPT; j++) {
            int p = slot * JPT + j;
            ull ox = offx[p], oy = offy[p];
#pragma unroll
            for (int g = 0; g < 4; g++)
                acc[g][j] = f2fma(a0[g], ox, f2fma(a1[g], oy, bb[g]));
        }
    }
    const float4* wp = wd + n;
    const float2* hp = hin + (size_t)slot * JPT * 128;
#pragma unroll 2
    for (int kk = 0; kk < 64; kk++) {
        ull w[4][2];
#pragma unroll
        for (int g = 0; g < 4; g++) {
            ulonglong2 lw = __ldg((const ulonglong2*)(wp + (g * 64 + kk) * 128));
            w[g][0] = lw.x; w[g][1] = lw.y;
        }
#pragma unroll
        for (int j = 0; j < JPT; j++) {
            ulonglong2 hv = *(const ulonglong2*)(hp + j * 128 + 2 * kk);
#pragma unroll
            for (int g = 0; g < 4; g++) {
                acc[g][j] = f2fma(w[g][0], hv.x, acc[g][j]);
                acc[g][j] = f2fma(w[g][1], hv.y, acc[g][j]);
            }
        }
    }
#pragma unroll
    for (int j = 0; j < JPT; j++) {
        int p = slot * JPT + j;
        float2 iv = unpk(acc[0][j]);
        float2 fv = unpk(acc[1][j]);
        float2 gv = unpk(acc[2][j]);
        float2 ov = unpk(acc[3][j]);
        float2 cv = c_s[p * 128 + n];
        float c0 = sigmf_(fv.x) * cv.x + sigmf_(iv.x) * tanhf_(gv.x);
        float c1 = sigmf_(fv.y) * cv.y + sigmf_(iv.y) * tanhf_(gv.y);
        c_s[p * 128 + n] = make_float2(c0, c1);
        hout[p * 128 + n] = make_float2(sigmf_(ov.x) * tanhf_(c0),
                                        sigmf_(ov.y) * tanhf_(c1));
    }
}

__global__ void __launch_bounds__(512, 1)
k_main(const float* __restrict__ obs, const float* __restrict__ bm1,
       const float* __restrict__ bm2, const float* __restrict__ Wr,
       const float* __restrict__ br, const float* __restrict__ z,
       float* __restrict__ out, int B, int T, int S)
{
    extern __shared__ char smem[];
    float2* hbuf0 = (float2*)smem;
    float2* hbuf1 = (float2*)(smem + 28672);
    float2* c_s   = (float2*)(smem + 57344);
    ull*    ab_s  = (ull*)(smem + 86016);
    char*   region = smem + 98304;
    ull*    offx_s = (ull*)region;
    ull*    offy_s = offx_s + TMAX * NPAIR;
    float2* m1_s   = (float2*)region;
    float2* base_s = (float2*)(smem + 155648);
    float*  offc   = (float*)(smem + 156160);   // x[56], y[56]
    float*  wr_s   = (float*)(smem + 156672);   // 256

    const int tid = threadIdx.x;
    const int n = tid & 127;
    const int slot = tid >> 7;
    const int b0 = blockIdx.x * ROWS;
    if (T > TMAX) T = TMAX;

    // ---- init: zero h0/c0, load encoder folded weights, build offsets ----
    for (int i = tid; i < NPAIR * 128; i += 512) {
        hbuf0[i] = make_float2(0.f, 0.f);
        c_s[i] = make_float2(0.f, 0.f);
    }
    for (int i = tid; i < 1536; i += 512) ab_s[i] = g_abE[i];
    if (tid < 256) wr_s[tid] = Wr[tid];

    for (int i = tid; i < ROWS * T; i += 512) {
        int r = i / T, t = i % T;
        int b = b0 + r;
        float ox = 0.f, oy = 0.f;
        float cx = 0.f, cy = 0.f;
        if (b < B) {
            cx = obs[((size_t)b * T + t) * 2 + 0];
            cy = obs[((size_t)b * T + t) * 2 + 1];
            float px = 0.f, py = 0.f;
            if (t > 0) {
                px = obs[((size_t)b * T + t - 1) * 2 + 0];
                py = obs[((size_t)b * T + t - 1) * 2 + 1];
            }
            ox = cx - px; oy = cy - py;
        }
        if (t == T - 1) base_s[r] = make_float2(cx, cy);
        ((float*)&offx_s[t * NPAIR + (r >> 1)])[r & 1] = ox;
        ((float*)&offy_s[t * NPAIR + (r >> 1)])[r & 1] = oy;
    }
    __syncthreads();

    float2* bufs[2] = {hbuf0, hbuf1};
    int par = 0;

    // ---- encoder ----
    for (int t = 0; t < T; t++) {
        lstm_step(bufs[par], bufs[par ^ 1], c_s, ab_s, g_wdupE,
                  &offx_s[t * NPAIR], &offy_s[t * NPAIR], n, slot);
        __syncthreads();
        par ^= 1;
    }

    // ---- save last offsets (decoder init input) + swap to decoder weights ----
    if (tid < NPAIR) {
        ((ull*)offc)[tid]        = offx_s[(T - 1) * NPAIR + tid];
        ((ull*)(offc + ROWS))[tid] = offy_s[(T - 1) * NPAIR + tid];
    }
    for (int i = tid; i < 1536; i += 512) ab_s[i] = g_abD[i];
    __syncthreads();

    // ---- MLP layer 1: m1 = relu(Wm1 @ hF + bm1) (outs n and n+128) ----
    {
        const float2* hf = bufs[par];
        ull acc1[2][JPT];
        float b0f = bm1[n], b1f = bm1[n + 128];
#pragma unroll
        for (int j = 0; j < JPT; j++) { acc1[0][j] = pk(b0f, b0f); acc1[1][j] = pk(b1f, b1f); }
        const float2* hp = hf + (size_t)slot * JPT * 128;
        for (int kk = 0; kk < 64; kk++) {
            float wA0 = g_Wm1T[(2 * kk) * 256 + n];
            float wA1 = g_Wm1T[(2 * kk + 1) * 256 + n];
            float wB0 = g_Wm1T[(2 * kk) * 256 + n + 128];
            float wB1 = g_Wm1T[(2 * kk + 1) * 256 + n + 128];
            ull w00 = pk(wA0, wA0), w01 = pk(wA1, wA1);
            ull w10 = pk(wB0, wB0), w11 = pk(wB1, wB1);
#pragma unroll
            for (int j = 0; j < JPT; j++) {
                ulonglong2 hv = *(const ulonglong2*)(hp + j * 128 + 2 * kk);
                acc1[0][j] = f2fma(w00, hv.x, acc1[0][j]);
                acc1[0][j] = f2fma(w01, hv.y, acc1[0][j]);
                acc1[1][j] = f2fma(w10, hv.x, acc1[1][j]);
                acc1[1][j] = f2fma(w11, hv.y, acc1[1][j]);
            }
        }
        __syncthreads();  // reads of offsets region done before m1_s overwrite
#pragma unroll
        for (int j = 0; j < JPT; j++) {
            int p = slot * JPT + j;
            float2 v0 = unpk(acc1[0][j]);
            float2 v1 = unpk(acc1[1][j]);
            m1_s[p * 256 + n]       = make_float2(fmaxf(v0.x, 0.f), fmaxf(v0.y, 0.f));
            m1_s[p * 256 + n + 128] = make_float2(fmaxf(v1.x, 0.f), fmaxf(v1.y, 0.f));
        }
    }
    __syncthreads();

    // ---- MLP layer 2 + concat(z) -> dh written into bufs[par]; reset c ----
    {
        float2* hwr = bufs[par];
        if (n < 112) {
            ull acc2[JPT];
            float bb2 = bm2[n];
#pragma unroll
            for (int j = 0; j < JPT; j++) acc2[j] = pk(bb2, bb2);
            const float2* mp = m1_s + (size_t)slot * JPT * 256;
            for (int kk = 0; kk < 128; kk++) {
                float w0 = g_Wm2T[(2 * kk) * 112 + n];
                float w1 = g_Wm2T[(2 * kk + 1) * 112 + n];
                ull W0 = pk(w0, w0), W1 = pk(w1, w1);
#pragma unroll
                for (int j = 0; j < JPT; j++) {
                    ulonglong2 mv = *(const ulonglong2*)(mp + j * 256 + 2 * kk);
                    acc2[j] = f2fma(W0, mv.x, acc2[j]);
                    acc2[j] = f2fma(W1, mv.y, acc2[j]);
                }
            }
#pragma unroll
            for (int j = 0; j < JPT; j++) {
                int p = slot * JPT + j;
                float2 v = unpk(acc2[j]);
                hwr[p * 128 + n] = make_float2(fmaxf(v.x, 0.f), fmaxf(v.y, 0.f));
            }
        }
        {   // z concat: thread -> (pair, zz)
            int p = tid >> 4, zz = tid & 15;
            if (p < NPAIR) {
                int r0 = b0 + 2 * p, r1 = r0 + 1;
                float z0 = (r0 < B) ? z[(size_t)r0 * 16 + zz] : 0.f;
                float z1 = (r1 < B) ? z[(size_t)r1 * 16 + zz] : 0.f;
                hwr[p * 128 + 112 + zz] = make_float2(z0, z1);
            }
        }
        for (int i = tid; i < NPAIR * 128; i += 512) c_s[i] = make_float2(0.f, 0.f);
    }
    __syncthreads();

    // ---- decoder ----
    const int wwid = tid >> 5, lid = tid & 31;
    const int row_l = 4 * wwid + (lid >> 3);          // 0..63
    const bool row_ok = (row_l < ROWS);
    const int row_c = row_ok ? row_l : 0;
    const int kb = lid & 7;
    const bool rlead = row_ok && ((lid & 7) == 0);
    float2 mybase = base_s[row_c];
    float2 oacc = make_float2(0.f, 0.f);
    float br0 = br[0], br1 = br[1];

    for (int s = 0; s < S; s++) {
        lstm_step(bufs[par], bufs[par ^ 1], c_s, ab_s, g_wdupD,
                  (const ull*)offc, (const ull*)(offc + ROWS), n, slot);
        __syncthreads();
        // readout: off = Wr @ h_new + br ; cumsum output
        const float* hv2 = (const float*)bufs[par ^ 1];
        float p0 = 0.f, p1 = 0.f;
        int bidx = (row_c >> 1) * 256 + (row_c & 1);
#pragma unroll 4
        for (int m = 0; m < 16; m++) {
            int k = kb + 8 * m;
            float hvv = hv2[bidx + 2 * k];
            p0 += wr_s[k] * hvv;
            p1 += wr_s[128 + k] * hvv;
        }
        p0 += __shfl_xor_sync(0xffffffffu, p0, 1);
        p0 += __shfl_xor_sync(0xffffffffu, p0, 2);
        p0 += __shfl_xor_sync(0xffffffffu, p0, 4);
        p1 += __shfl_xor_sync(0xffffffffu, p1, 1);
        p1 += __shfl_xor_sync(0xffffffffu, p1, 2);
        p1 += __shfl_xor_sync(0xffffffffu, p1, 4);
        if (rlead) {
            float ox = p0 + br0, oy = p1 + br1;
            oacc.x += ox; oacc.y += oy;
            offc[row_l] = ox;
            offc[ROWS + row_l] = oy;
            int b = b0 + row_l;
            if (b < B) {
                out[((size_t)b * S + s) * 2 + 0] = mybase.x + oacc.x;
                out[((size_t)b * S + s) * 2 + 1] = mybase.y + oacc.y;
            }
        }
        __syncthreads();
        par ^= 1;
    }
}

// ---------------- launch ------------------------------------------------------
extern "C" void kernel_launch(void* const* d_in, const int* in_sizes, int n_in,
                              void* d_out, int out_size) {
    const float* obs   = (const float*)d_in[0];
    const float* We    = (const float*)d_in[2];
    const float* be    = (const float*)d_in[3];
    const float* Wih_e = (const float*)d_in[4];
    const float* Whh_e = (const float*)d_in[5];
    const float* b_e   = (const float*)d_in[6];
    const float* Wm1   = (const float*)d_in[7];
    const float* bm1   = (const float*)d_in[8];
    const float* Wm2   = (const float*)d_in[9];
    const float* bm2   = (const float*)d_in[10];
    const float* Wd    = (const float*)d_in[11];
    const float* bd    = (const float*)d_in[12];
    const float* Wih_d = (const float*)d_in[13];
    const float* Whh_d = (const float*)d_in[14];
    const float* b_d   = (const float*)d_in[15];
    const float* Wr    = (const float*)d_in[16];
    const float* br    = (const float*)d_in[17];
    const float* z     = (const float*)d_in[18];
    float* out = (float*)d_out;

    int NZ = 16;
    int B = in_sizes[18] / NZ;
    int T = in_sizes[0] / (B * 2);
    int S = out_size / (B * 2);
    int E = in_sizes[2] / 2;

    k_prep<<<256, 256>>>(Wih_e, We, be, b_e, Wih_d, Wd, bd, b_d,
                         Whh_e, Whh_d, Wm1, Wm2, E);

    cudaFuncSetAttribute(k_main, cudaFuncAttributeMaxDynamicSharedMemorySize, SMEM_BYTES);
    int grid = (B + ROWS - 1) / ROWS;
    k_main<<<grid, 512, SMEM_BYTES>>>(obs, bm1, bm2, Wr, br, z, out, B, T, S);
}

// round 4
// speedup vs baseline: 1.3490x; 1.1309x over previous
#include <cuda_runtime.h>
#include <cuda_bf16.h>
#include <cstdint>

typedef unsigned long long ull;

// ---------------- device-global scratch (no runtime alloc allowed) -------------
// Undup weight tables: [g][kk][n] float2 = {w[g,n,2kk], w[g,n,2kk+1]}  (256KB each)
__device__ float2 g_wuE[4 * 64 * 128];
__device__ float2 g_wuD[4 * 64 * 128];
__device__ ull    g_abE[128 * 4 * 3];      // per (n,gate): {bias,bias},{a0,a0},{a1,a1}
__device__ ull    g_abD[128 * 4 * 3];
__device__ float  g_Wm1T[128 * 256];       // [k][mc]
__device__ float  g_Wm2T[256 * 112];       // [k][mc]

// ---------------- f32x2 helpers ------------------------------------------------
__device__ __forceinline__ ull f2fma(ull a, ull b, ull c) {
    ull d;
    asm("fma.rn.f32x2 %0, %1, %2, %3;" : "=l"(d) : "l"(a), "l"(b), "l"(c));
    return d;
}
__device__ __forceinline__ ull pk(float lo, float hi) {
    ull r;
    asm("mov.b64 %0, {%1, %2};" : "=l"(r) : "f"(lo), "f"(hi));
    return r;
}
__device__ __forceinline__ float2 unpk(ull v) {
    float2 r;
    asm("mov.b64 {%0, %1}, %2;" : "=f"(r.x), "=f"(r.y) : "l"(v));
    return r;
}
__device__ __forceinline__ float sigmf_(float x) {
    return __fdividef(1.0f, 1.0f + __expf(-x));
}
__device__ __forceinline__ float tanhf_(float x) {
    x = fminf(fmaxf(x, -15.0f), 15.0f);
    float e = __expf(-2.0f * x);
    return __fdividef(1.0f - e, 1.0f + e);
}

// ---------------- fused precompute kernel --------------------------------------
__global__ void k_prep(const float* __restrict__ Wih_e, const float* __restrict__ We,
                       const float* __restrict__ be,   const float* __restrict__ b_e,
                       const float* __restrict__ Wih_d, const float* __restrict__ Wd,
                       const float* __restrict__ bd,   const float* __restrict__ b_d,
                       const float* __restrict__ Whh_e, const float* __restrict__ Whh_d,
                       const float* __restrict__ Wm1,  const float* __restrict__ Wm2,
                       int E)
{
    int idx0 = blockIdx.x * blockDim.x + threadIdx.x;
    int stride = gridDim.x * blockDim.x;

    // fold A = Wih @ Win (512x2), bias = Wih @ bin + bgate  (encoder + decoder)
    for (int i = idx0; i < 1024; i += stride) {
        int which = i >> 9;          // 0 = enc, 1 = dec
        int gn = i & 511;
        const float* Wih = which ? Wih_d : Wih_e;
        const float* Win = which ? Wd : We;
        const float* bin = which ? bd : be;
        const float* bg  = which ? b_d : b_e;
        ull* ab_out = which ? g_abD : g_abE;
        float a0 = 0.f, a1 = 0.f, bb = 0.f;
        for (int e = 0; e < E; e++) {
            float w = Wih[gn * E + e];
            a0 += w * Win[e * 2 + 0];
            a1 += w * Win[e * 2 + 1];
            bb += w * bin[e];
        }
        bb += bg[gn];
        int n = gn & 127, g = gn >> 7;
        ab_out[(n * 4 + g) * 3 + 0] = pk(bb, bb);
        ab_out[(n * 4 + g) * 3 + 1] = pk(a0, a0);
        ab_out[(n * 4 + g) * 3 + 2] = pk(a1, a1);
    }

    // undup n-coalesced Whh layout: [ (g*64+kk)*128 + n ] = {w(2kk), w(2kk+1)}
    for (int i = idx0; i < 2 * 4 * 64 * 128; i += stride) {
        int which = i >= 32768;
        int idx = i & 32767;
        const float* Whh = which ? Whh_d : Whh_e;
        float2* out = which ? g_wuD : g_wuE;
        int n = idx & 127;
        int kk = (idx >> 7) & 63;
        int g = idx >> 13;
        float w0 = Whh[(g * 128 + n) * 128 + 2 * kk + 0];
        float w1 = Whh[(g * 128 + n) * 128 + 2 * kk + 1];
        out[idx] = make_float2(w0, w1);
    }

    // MLP weight transposes
    for (int j = idx0; j < 128 * 256; j += stride) {
        int k = j >> 8, mc = j & 255;
        g_Wm1T[j] = Wm1[mc * 128 + k];
    }
    for (int j = idx0; j < 256 * 112; j += stride) {
        int k = j / 112, mc = j % 112;
        g_Wm2T[j] = Wm2[mc * 256 + k];
    }
}

// ---------------- main persistent kernel ---------------------------------------
// 512 threads, 56 rows (28 pairs) per block. thread: n = tid&127, slot = tid>>7.
// Each slot owns 7 pairs. h, c pair-packed in smem: [pair][k] float2.

#define ROWS  56
#define NPAIR 28
#define JPT   7
#define TMAX  50

// smem layout (bytes):
//  hbuf0 : 0       28672
//  hbuf1 : 28672   28672
//  c_s   : 57344   28672
//  ab_s  : 86016   12288
//  region: 98304   57344   (offsets: TMAX*NPAIR ull x + y = 22400 | m1: 28*256 f2 = 57344)
//  base_s: 155648  512     (56 float2)
//  offc  : 156160  512     (x[56], y[56] floats)
//  wr_s  : 156672  1024
#define SMEM_BYTES 157696

__device__ __forceinline__ void lstm_step(
    const float2* __restrict__ hin, float2* __restrict__ hout,
    float2* __restrict__ c_s, const ull* __restrict__ ab_s,
    const float2* __restrict__ wd,
    const ull* __restrict__ offx, const ull* __restrict__ offy,
    int n, int slot)
{
    ull acc[4][JPT];
    {
        ull bb[4], a0[4], a1[4];
#pragma unroll
        for (int g = 0; g < 4; g++) {
            const ull* q = &ab_s[(n * 4 + g) * 3];
            bb[g] = q[0]; a0[g] = q[1]; a1[g] = q[2];
        }
#pragma unroll
        for (int j = 0; j < JPT; j++) {
            int p = slot * JPT + j;
            ull ox = offx[p], oy = offy[p];
#pragma unroll
            for (int g = 0; g < 4; g++)
                acc[g][j] = f2fma(a0[g], ox, f2fma(a1[g], oy, bb[g]));
        }
    }
    const float2* wp = wd + n;
    const float2* hp = hin + (size_t)slot * JPT * 128;
#pragma unroll 2
    for (int kk = 0; kk < 64; kk++) {
        // undup weight load: {w(2kk), w(2kk+1)} per gate, 8B/lane -> 2 wf
        float2 w[4];
#pragma unroll
        for (int g = 0; g < 4; g++)
            w[g] = __ldg(wp + (g * 64 + kk) * 128);
        // in-register duplication for the packed-f32x2 multiplier
        ull wa[4], wb[4];
#pragma unroll
        for (int g = 0; g < 4; g++) {
            wa[g] = pk(w[g].x, w[g].x);
            wb[g] = pk(w[g].y, w[g].y);
        }
#pragma unroll
        for (int j = 0; j < JPT; j++) {
            ulonglong2 hv = *(const ulonglong2*)(hp + j * 128 + 2 * kk);
#pragma unroll
            for (int g = 0; g < 4; g++) {
                acc[g][j] = f2fma(wa[g], hv.x, acc[g][j]);
                acc[g][j] = f2fma(wb[g], hv.y, acc[g][j]);
            }
        }
    }
#pragma unroll
    for (int j = 0; j < JPT; j++) {
        int p = slot * JPT + j;
        float2 iv = unpk(acc[0][j]);
        float2 fv = unpk(acc[1][j]);
        float2 gv = unpk(acc[2][j]);
        float2 ov = unpk(acc[3][j]);
        float2 cv = c_s[p * 128 + n];
        float c0 = sigmf_(fv.x) * cv.x + sigmf_(iv.x) * tanhf_(gv.x);
        float c1 = sigmf_(fv.y) * cv.y + sigmf_(iv.y) * tanhf_(gv.y);
        c_s[p * 128 + n] = make_float2(c0, c1);
        hout[p * 128 + n] = make_float2(sigmf_(ov.x) * tanhf_(c0),
                                        sigmf_(ov.y) * tanhf_(c1));
    }
}

__global__ void __launch_bounds__(512, 1)
k_main(const float* __restrict__ obs, const float* __restrict__ bm1,
       const float* __restrict__ bm2, const float* __restrict__ Wr,
       const float* __restrict__ br, const float* __restrict__ z,
       float* __restrict__ out, int B, int T, int S)
{
    extern __shared__ char smem[];
    float2* hbuf0 = (float2*)smem;
    float2* hbuf1 = (float2*)(smem + 28672);
    float2* c_s   = (float2*)(smem + 57344);
    ull*    ab_s  = (ull*)(smem + 86016);
    char*   region = smem + 98304;
    ull*    offx_s = (ull*)region;
    ull*    offy_s = offx_s + TMAX * NPAIR;
    float2* m1_s   = (float2*)region;
    float2* base_s = (float2*)(smem + 155648);
    float*  offc   = (float*)(smem + 156160);   // x[56], y[56]
    float*  wr_s   = (float*)(smem + 156672);   // 256

    const int tid = threadIdx.x;
    const int n = tid & 127;
    const int slot = tid >> 7;
    const int b0 = blockIdx.x * ROWS;
    if (T > TMAX) T = TMAX;

    // ---- init: zero h0/c0, load encoder folded weights, build offsets ----
    for (int i = tid; i < NPAIR * 128; i += 512) {
        hbuf0[i] = make_float2(0.f, 0.f);
        c_s[i] = make_float2(0.f, 0.f);
    }
    for (int i = tid; i < 1536; i += 512) ab_s[i] = g_abE[i];
    if (tid < 256) wr_s[tid] = Wr[tid];

    for (int i = tid; i < ROWS * T; i += 512) {
        int r = i / T, t = i % T;
        int b = b0 + r;
        float ox = 0.f, oy = 0.f;
        float cx = 0.f, cy = 0.f;
        if (b < B) {
            cx = obs[((size_t)b * T + t) * 2 + 0];
            cy = obs[((size_t)b * T + t) * 2 + 1];
            float px = 0.f, py = 0.f;
            if (t > 0) {
                px = obs[((size_t)b * T + t - 1) * 2 + 0];
                py = obs[((size_t)b * T + t - 1) * 2 + 1];
            }
            ox = cx - px; oy = cy - py;
        }
        if (t == T - 1) base_s[r] = make_float2(cx, cy);
        ((float*)&offx_s[t * NPAIR + (r >> 1)])[r & 1] = ox;
        ((float*)&offy_s[t * NPAIR + (r >> 1)])[r & 1] = oy;
    }
    __syncthreads();

    float2* bufs[2] = {hbuf0, hbuf1};
    int par = 0;

    // ---- encoder ----
    for (int t = 0; t < T; t++) {
        lstm_step(bufs[par], bufs[par ^ 1], c_s, ab_s, g_wuE,
                  &offx_s[t * NPAIR], &offy_s[t * NPAIR], n, slot);
        __syncthreads();
        par ^= 1;
    }

    // ---- save last offsets (decoder init input) + swap to decoder weights ----
    if (tid < NPAIR) {
        ((ull*)offc)[tid]          = offx_s[(T - 1) * NPAIR + tid];
        ((ull*)(offc + ROWS))[tid] = offy_s[(T - 1) * NPAIR + tid];
    }
    for (int i = tid; i < 1536; i += 512) ab_s[i] = g_abD[i];
    __syncthreads();

    // ---- MLP layer 1: m1 = relu(Wm1 @ hF + bm1) (outs n and n+128) ----
    {
        const float2* hf = bufs[par];
        ull acc1[2][JPT];
        float b0f = bm1[n], b1f = bm1[n + 128];
#pragma unroll
        for (int j = 0; j < JPT; j++) { acc1[0][j] = pk(b0f, b0f); acc1[1][j] = pk(b1f, b1f); }
        const float2* hp = hf + (size_t)slot * JPT * 128;
        for (int kk = 0; kk < 64; kk++) {
            float wA0 = g_Wm1T[(2 * kk) * 256 + n];
            float wA1 = g_Wm1T[(2 * kk + 1) * 256 + n];
            float wB0 = g_Wm1T[(2 * kk) * 256 + n + 128];
            float wB1 = g_Wm1T[(2 * kk + 1) * 256 + n + 128];
            ull w00 = pk(wA0, wA0), w01 = pk(wA1, wA1);
            ull w10 = pk(wB0, wB0), w11 = pk(wB1, wB1);
#pragma unroll
            for (int j = 0; j < JPT; j++) {
                ulonglong2 hv = *(const ulonglong2*)(hp + j * 128 + 2 * kk);
                acc1[0][j] = f2fma(w00, hv.x, acc1[0][j]);
                acc1[0][j] = f2fma(w01, hv.y, acc1[0][j]);
                acc1[1][j] = f2fma(w10, hv.x, acc1[1][j]);
                acc1[1][j] = f2fma(w11, hv.y, acc1[1][j]);
            }
        }
        __syncthreads();  // reads of offsets region done before m1_s overwrite
#pragma unroll
        for (int j = 0; j < JPT; j++) {
            int p = slot * JPT + j;
            float2 v0 = unpk(acc1[0][j]);
            float2 v1 = unpk(acc1[1][j]);
            m1_s[p * 256 + n]       = make_float2(fmaxf(v0.x, 0.f), fmaxf(v0.y, 0.f));
            m1_s[p * 256 + n + 128] = make_float2(fmaxf(v1.x, 0.f), fmaxf(v1.y, 0.f));
        }
    }
    __syncthreads();

    // ---- MLP layer 2 + concat(z) -> dh written into bufs[par]; reset c ----
    {
        float2* hwr = bufs[par];
        if (n < 112) {
            ull acc2[JPT];
            float bb2 = bm2[n];
#pragma unroll
            for (int j = 0; j < JPT; j++) acc2[j] = pk(bb2, bb2);
            const float2* mp = m1_s + (size_t)slot * JPT * 256;
            for (int kk = 0; kk < 128; kk++) {
                float w0 = g_Wm2T[(2 * kk) * 112 + n];
                float w1 = g_Wm2T[(2 * kk + 1) * 112 + n];
                ull W0 = pk(w0, w0), W1 = pk(w1, w1);
#pragma unroll
                for (int j = 0; j < JPT; j++) {
                    ulonglong2 mv = *(const ulonglong2*)(mp + j * 256 + 2 * kk);
                    acc2[j] = f2fma(W0, mv.x, acc2[j]);
                    acc2[j] = f2fma(W1, mv.y, acc2[j]);
                }
            }
#pragma unroll
            for (int j = 0; j < JPT; j++) {
                int p = slot * JPT + j;
                float2 v = unpk(acc2[j]);
                hwr[p * 128 + n] = make_float2(fmaxf(v.x, 0.f), fmaxf(v.y, 0.f));
            }
        }
        {   // z concat: thread -> (pair, zz)
            int p = tid >> 4, zz = tid & 15;
            if (p < NPAIR) {
                int r0 = b0 + 2 * p, r1 = r0 + 1;
                float z0 = (r0 < B) ? z[(size_t)r0 * 16 + zz] : 0.f;
                float z1 = (r1 < B) ? z[(size_t)r1 * 16 + zz] : 0.f;
                hwr[p * 128 + 112 + zz] = make_float2(z0, z1);
            }
        }
        for (int i = tid; i < NPAIR * 128; i += 512) c_s[i] = make_float2(0.f, 0.f);
    }
    __syncthreads();

    // ---- decoder ----
    const int wwid = tid >> 5, lid = tid & 31;
    const int row_l = 4 * wwid + (lid >> 3);          // 0..63
    const bool row_ok = (row_l < ROWS);
    const int row_c = row_ok ? row_l : 0;
    const int kb = lid & 7;
    const bool rlead = row_ok && ((lid & 7) == 0);
    float2 mybase = base_s[row_c];
    float2 oacc = make_float2(0.f, 0.f);
    float br0 = br[0], br1 = br[1];

    for (int s = 0; s < S; s++) {
        lstm_step(bufs[par], bufs[par ^ 1], c_s, ab_s, g_wuD,
                  (const ull*)offc, (const ull*)(offc + ROWS), n, slot);
        __syncthreads();
        // readout: off = Wr @ h_new + br ; cumsum output
        const float* hv2 = (const float*)bufs[par ^ 1];
        float p0 = 0.f, p1 = 0.f;
        int bidx = (row_c >> 1) * 256 + (row_c & 1);
#pragma unroll 4
        for (int m = 0; m < 16; m++) {
            int k = kb + 8 * m;
            float hvv = hv2[bidx + 2 * k];
            p0 += wr_s[k] * hvv;
            p1 += wr_s[128 + k] * hvv;
        }
        p0 += __shfl_xor_sync(0xffffffffu, p0, 1);
        p0 += __shfl_xor_sync(0xffffffffu, p0, 2);
        p0 += __shfl_xor_sync(0xffffffffu, p0, 4);
        p1 += __shfl_xor_sync(0xffffffffu, p1, 1);
        p1 += __shfl_xor_sync(0xffffffffu, p1, 2);
        p1 += __shfl_xor_sync(0xffffffffu, p1, 4);
        if (rlead) {
            float ox = p0 + br0, oy = p1 + br1;
            oacc.x += ox; oacc.y += oy;
            offc[row_l] = ox;
            offc[ROWS + row_l] = oy;
            int b = b0 + row_l;
            if (b < B) {
                out[((size_t)b * S + s) * 2 + 0] = mybase.x + oacc.x;
                out[((size_t)b * S + s) * 2 + 1] = mybase.y + oacc.y;
            }
        }
        __syncthreads();
        par ^= 1;
    }
}

// ---------------- launch ------------------------------------------------------
extern "C" void kernel_launch(void* const* d_in, const int* in_sizes, int n_in,
                              void* d_out, int out_size) {
    const float* obs   = (const float*)d_in[0];
    const float* We    = (const float*)d_in[2];
    const float* be    = (const float*)d_in[3];
    const float* Wih_e = (const float*)d_in[4];
    const float* Whh_e = (const float*)d_in[5];
    const float* b_e   = (const float*)d_in[6];
    const float* Wm1   = (const float*)d_in[7];
    const float* bm1   = (const float*)d_in[8];
    const float* Wm2   = (const float*)d_in[9];
    const float* bm2   = (const float*)d_in[10];
    const float* Wd    = (const float*)d_in[11];
    const float* bd    = (const float*)d_in[12];
    const float* Wih_d = (const float*)d_in[13];
    const float* Whh_d = (const float*)d_in[14];
    const float* b_d   = (const float*)d_in[15];
    const float* Wr    = (const float*)d_in[16];
    const float* br    = (const float*)d_in[17];
    const float* z     = (const float*)d_in[18];
    float* out = (float*)d_out;

    int NZ = 16;
    int B = in_sizes[18] / NZ;
    int T = in_sizes[0] / (B * 2);
    int S = out_size / (B * 2);
    int E = in_sizes[2] / 2;

    k_prep<<<256, 256>>>(Wih_e, We, be, b_e, Wih_d, Wd, bd, b_d,
                         Whh_e, Whh_d, Wm1, Wm2, E);

    cudaFuncSetAttribute(k_main, cudaFuncAttributeMaxDynamicSharedMemorySize, SMEM_BYTES);
    int grid = (B + ROWS - 1) / ROWS;
    k_main<<<grid, 512, SMEM_BYTES>>>(obs, bm1, bm2, Wr, br, z, out, B, T, S);
}

// round 5
// speedup vs baseline: 1.4964x; 1.1093x over previous
#include <cuda_runtime.h>
#include <cuda_bf16.h>
#include <cstdint>

typedef unsigned long long ull;

// ---------------- device-global scratch (no runtime alloc allowed) -------------
// Weight tables in kk-major layout for chunked smem staging:
//   [kk][g][n] float2 = {w[g,n,2kk], w[g,n,2kk+1]}   (64*4*128 float2 = 256KB each)
__device__ float2 g_wsE[64 * 4 * 128];
__device__ float2 g_wsD[64 * 4 * 128];
__device__ ull    g_abE[128 * 4 * 3];      // per (n,gate): {bias,bias},{a0,a0},{a1,a1}
__device__ ull    g_abD[128 * 4 * 3];
__device__ float  g_Wm1T[128 * 256];       // [k][mc]
__device__ float  g_Wm2T[256 * 112];       // [k][mc]

// ---------------- f32x2 + async helpers ----------------------------------------
__device__ __forceinline__ ull f2fma(ull a, ull b, ull c) {
    ull d;
    asm("fma.rn.f32x2 %0, %1, %2, %3;" : "=l"(d) : "l"(a), "l"(b), "l"(c));
    return d;
}
__device__ __forceinline__ ull pk(float lo, float hi) {
    ull r;
    asm("mov.b64 %0, {%1, %2};" : "=l"(r) : "f"(lo), "f"(hi));
    return r;
}
__device__ __forceinline__ float2 unpk(ull v) {
    float2 r;
    asm("mov.b64 {%0, %1}, %2;" : "=f"(r.x), "=f"(r.y) : "l"(v));
    return r;
}
__device__ __forceinline__ void cp_async16(uint32_t saddr, const void* gptr) {
    asm volatile("cp.async.cg.shared.global [%0], [%1], 16;" :: "r"(saddr), "l"(gptr));
}
__device__ __forceinline__ float sigmf_(float x) {
    return __fdividef(1.0f, 1.0f + __expf(-x));
}
__device__ __forceinline__ float tanhf_(float x) {
    x = fminf(fmaxf(x, -15.0f), 15.0f);
    float e = __expf(-2.0f * x);
    return __fdividef(1.0f - e, 1.0f + e);
}

// ---------------- fused precompute kernel --------------------------------------
__global__ void k_prep(const float* __restrict__ Wih_e, const float* __restrict__ We,
                       const float* __restrict__ be,   const float* __restrict__ b_e,
                       const float* __restrict__ Wih_d, const float* __restrict__ Wd,
                       const float* __restrict__ bd,   const float* __restrict__ b_d,
                       const float* __restrict__ Whh_e, const float* __restrict__ Whh_d,
                       const float* __restrict__ Wm1,  const float* __restrict__ Wm2,
                       int E)
{
    int idx0 = blockIdx.x * blockDim.x + threadIdx.x;
    int stride = gridDim.x * blockDim.x;

    // fold A = Wih @ Win (512x2), bias = Wih @ bin + bgate  (encoder + decoder)
    for (int i = idx0; i < 1024; i += stride) {
        int which = i >> 9;          // 0 = enc, 1 = dec
        int gn = i & 511;
        const float* Wih = which ? Wih_d : Wih_e;
        const float* Win = which ? Wd : We;
        const float* bin = which ? bd : be;
        const float* bg  = which ? b_d : b_e;
        ull* ab_out = which ? g_abD : g_abE;
        float a0 = 0.f, a1 = 0.f, bb = 0.f;
        for (int e = 0; e < E; e++) {
            float w = Wih[gn * E + e];
            a0 += w * Win[e * 2 + 0];
            a1 += w * Win[e * 2 + 1];
            bb += w * bin[e];
        }
        bb += bg[gn];
        int n = gn & 127, g = gn >> 7;
        ab_out[(n * 4 + g) * 3 + 0] = pk(bb, bb);
        ab_out[(n * 4 + g) * 3 + 1] = pk(a0, a0);
        ab_out[(n * 4 + g) * 3 + 2] = pk(a1, a1);
    }

    // kk-major Whh layout: idx = kk*512 + g*128 + n  ->  {w(2kk), w(2kk+1)}
    for (int i = idx0; i < 2 * 32768; i += stride) {
        int which = i >= 32768;
        int idx = i & 32767;
        const float* Whh = which ? Whh_d : Whh_e;
        float2* out = which ? g_wsD : g_wsE;
        int n = idx & 127;
        int g = (idx >> 7) & 3;
        int kk = idx >> 9;
        float w0 = Whh[(g * 128 + n) * 128 + 2 * kk + 0];
        float w1 = Whh[(g * 128 + n) * 128 + 2 * kk + 1];
        out[idx] = make_float2(w0, w1);
    }

    // MLP weight transposes
    for (int j = idx0; j < 128 * 256; j += stride) {
        int k = j >> 8, mc = j & 255;
        g_Wm1T[j] = Wm1[mc * 128 + k];
    }
    for (int j = idx0; j < 256 * 112; j += stride) {
        int k = j / 112, mc = j % 112;
        g_Wm2T[j] = Wm2[mc * 256 + k];
    }
}

// ---------------- main persistent kernel ---------------------------------------
// 512 threads, 56 rows (28 pairs) per block. thread: n = tid&127, slot = tid>>7.
// Each slot owns 7 pairs. h, c pair-packed in smem: [pair][k] float2.

#define ROWS  56
#define NPAIR 28
#define JPT   7
#define TMAX  50

// smem layout (bytes):
//  hbuf0 : 0       28672
//  hbuf1 : 28672   28672
//  c_s   : 57344   28672
//  ab_s  : 86016   12288
//  region: 98304   57344   (offsets: TMAX*NPAIR ull x + y = 22400 | m1: 28*256 f2 = 57344)
//  base_s: 155648  512     (56 float2)
//  offc  : 156160  512     (x[56], y[56] floats)
//  wr_s  : 156672  1024
//  wstage: 157696  65536   (2 x 32KB weight chunk buffers)
#define WSTAGE_OFF 157696
#define SMEM_BYTES 223232

__device__ __forceinline__ void lstm_step(
    const float2* __restrict__ hin, float2* __restrict__ hout,
    float2* __restrict__ c_s, const ull* __restrict__ ab_s,
    const float2* __restrict__ wd,      // gmem weights, [kk][g][n] float2
    float2* __restrict__ wstage,        // smem, 2 buffers of 4096 float2
    const ull* __restrict__ offx, const ull* __restrict__ offy,
    int n, int slot, int tid)
{
    ull acc[4][JPT];
    {
        ull bb[4], a0[4], a1[4];
#pragma unroll
        for (int g = 0; g < 4; g++) {
            const ull* q = &ab_s[(n * 4 + g) * 3];
            bb[g] = q[0]; a0[g] = q[1]; a1[g] = q[2];
        }
#pragma unroll
        for (int j = 0; j < JPT; j++) {
            int p = slot * JPT + j;
            ull ox = offx[p], oy = offy[p];
#pragma unroll
            for (int g = 0; g < 4; g++)
                acc[g][j] = f2fma(a0[g], ox, f2fma(a1[g], oy, bb[g]));
        }
    }

    const uint32_t ws_base = (uint32_t)__cvta_generic_to_shared(wstage);

    // issue chunk 0 (32KB: 2048 x 16B, 4 per thread)
    {
        const char* src = (const char*)wd + tid * 16;
        uint32_t dst = ws_base + tid * 16;
#pragma unroll
        for (int k = 0; k < 4; k++)
            cp_async16(dst + k * 8192, src + k * 8192);
        asm volatile("cp.async.commit_group;" ::: "memory");
    }

    const float2* hp = hin + (size_t)slot * JPT * 128;

#pragma unroll 1
    for (int c = 0; c < 8; c++) {
        if (c < 7) {
            const char* src = (const char*)(wd + (c + 1) * 4096) + tid * 16;
            uint32_t dst = ws_base + ((c + 1) & 1) * 32768 + tid * 16;
#pragma unroll
            for (int k = 0; k < 4; k++)
                cp_async16(dst + k * 8192, src + k * 8192);
            asm volatile("cp.async.commit_group;" ::: "memory");
            asm volatile("cp.async.wait_group 1;" ::: "memory");
        } else {
            asm volatile("cp.async.wait_group 0;" ::: "memory");
        }
        __syncthreads();

        const float2* wb = wstage + (c & 1) * 4096;
#pragma unroll
        for (int kkl = 0; kkl < 8; kkl++) {
            int kk = c * 8 + kkl;
            float2 w[4];
#pragma unroll
            for (int g = 0; g < 4; g++)
                w[g] = wb[((kkl * 4 + g) << 7) + n];
            ull wa[4], wv[4];
#pragma unroll
            for (int g = 0; g < 4; g++) {
                wa[g] = pk(w[g].x, w[g].x);
                wv[g] = pk(w[g].y, w[g].y);
            }
#pragma unroll
            for (int j = 0; j < JPT; j++) {
                ulonglong2 hv = *(const ulonglong2*)(hp + j * 128 + 2 * kk);
#pragma unroll
                for (int g = 0; g < 4; g++) {
                    acc[g][j] = f2fma(wa[g], hv.x, acc[g][j]);
                    acc[g][j] = f2fma(wv[g], hv.y, acc[g][j]);
                }
            }
        }
        __syncthreads();
    }

#pragma unroll
    for (int j = 0; j < JPT; j++) {
        int p = slot * JPT + j;
        float2 iv = unpk(acc[0][j]);
        float2 fv = unpk(acc[1][j]);
        float2 gv = unpk(acc[2][j]);
        float2 ov = unpk(acc[3][j]);
        float2 cv = c_s[p * 128 + n];
        float c0 = sigmf_(fv.x) * cv.x + sigmf_(iv.x) * tanhf_(gv.x);
        float c1 = sigmf_(fv.y) * cv.y + sigmf_(iv.y) * tanhf_(gv.y);
        c_s[p * 128 + n] = make_float2(c0, c1);
        hout[p * 128 + n] = make_float2(sigmf_(ov.x) * tanhf_(c0),
                                        sigmf_(ov.y) * tanhf_(c1));
    }
}

__global__ void __launch_bounds__(512, 1)
k_main(const float* __restrict__ obs, const float* __restrict__ bm1,
       const float* __restrict__ bm2, const float* __restrict__ Wr,
       const float* __restrict__ br, const float* __restrict__ z,
       float* __restrict__ out, int B, int T, int S)
{
    extern __shared__ char smem[];
    float2* hbuf0 = (float2*)smem;
    float2* hbuf1 = (float2*)(smem + 28672);
    float2* c_s   = (float2*)(smem + 57344);
    ull*    ab_s  = (ull*)(smem + 86016);
    char*   region = smem + 98304;
    ull*    offx_s = (ull*)region;
    ull*    offy_s = offx_s + TMAX * NPAIR;
    float2* m1_s   = (float2*)region;
    float2* base_s = (float2*)(smem + 155648);
    float*  offc   = (float*)(smem + 156160);   // x[56], y[56]
    float*  wr_s   = (float*)(smem + 156672);   // 256
    float2* wstage = (float2*)(smem + WSTAGE_OFF);

    const int tid = threadIdx.x;
    const int n = tid & 127;
    const int slot = tid >> 7;
    const int b0 = blockIdx.x * ROWS;
    if (T > TMAX) T = TMAX;

    // ---- init: zero h0/c0, load encoder folded weights, build offsets ----
    for (int i = tid; i < NPAIR * 128; i += 512) {
        hbuf0[i] = make_float2(0.f, 0.f);
        c_s[i] = make_float2(0.f, 0.f);
    }
    for (int i = tid; i < 1536; i += 512) ab_s[i] = g_abE[i];
    if (tid < 256) wr_s[tid] = Wr[tid];

    for (int i = tid; i < ROWS * T; i += 512) {
        int r = i / T, t = i % T;
        int b = b0 + r;
        float ox = 0.f, oy = 0.f;
        float cx = 0.f, cy = 0.f;
        if (b < B) {
            cx = obs[((size_t)b * T + t) * 2 + 0];
            cy = obs[((size_t)b * T + t) * 2 + 1];
            float px = 0.f, py = 0.f;
            if (t > 0) {
                px = obs[((size_t)b * T + t - 1) * 2 + 0];
                py = obs[((size_t)b * T + t - 1) * 2 + 1];
            }
            ox = cx - px; oy = cy - py;
        }
        if (t == T - 1) base_s[r] = make_float2(cx, cy);
        ((float*)&offx_s[t * NPAIR + (r >> 1)])[r & 1] = ox;
        ((float*)&offy_s[t * NPAIR + (r >> 1)])[r & 1] = oy;
    }
    __syncthreads();

    float2* bufs[2] = {hbuf0, hbuf1};
    int par = 0;

    // ---- encoder ----
    for (int t = 0; t < T; t++) {
        lstm_step(bufs[par], bufs[par ^ 1], c_s, ab_s, g_wsE, wstage,
                  &offx_s[t * NPAIR], &offy_s[t * NPAIR], n, slot, tid);
        __syncthreads();
        par ^= 1;
    }

    // ---- save last offsets (decoder init input) + swap to decoder weights ----
    if (tid < NPAIR) {
        ((ull*)offc)[tid]          = offx_s[(T - 1) * NPAIR + tid];
        ((ull*)(offc + ROWS))[tid] = offy_s[(T - 1) * NPAIR + tid];
    }
    for (int i = tid; i < 1536; i += 512) ab_s[i] = g_abD[i];
    __syncthreads();

    // ---- MLP layer 1: m1 = relu(Wm1 @ hF + bm1) (outs n and n+128) ----
    {
        const float2* hf = bufs[par];
        ull acc1[2][JPT];
        float b0f = bm1[n], b1f = bm1[n + 128];
#pragma unroll
        for (int j = 0; j < JPT; j++) { acc1[0][j] = pk(b0f, b0f); acc1[1][j] = pk(b1f, b1f); }
        const float2* hp = hf + (size_t)slot * JPT * 128;
        for (int kk = 0; kk < 64; kk++) {
            float wA0 = g_Wm1T[(2 * kk) * 256 + n];
            float wA1 = g_Wm1T[(2 * kk + 1) * 256 + n];
            float wB0 = g_Wm1T[(2 * kk) * 256 + n + 128];
            float wB1 = g_Wm1T[(2 * kk + 1) * 256 + n + 128];
            ull w00 = pk(wA0, wA0), w01 = pk(wA1, wA1);
            ull w10 = pk(wB0, wB0), w11 = pk(wB1, wB1);
#pragma unroll
            for (int j = 0; j < JPT; j++) {
                ulonglong2 hv = *(const ulonglong2*)(hp + j * 128 + 2 * kk);
                acc1[0][j] = f2fma(w00, hv.x, acc1[0][j]);
                acc1[0][j] = f2fma(w01, hv.y, acc1[0][j]);
                acc1[1][j] = f2fma(w10, hv.x, acc1[1][j]);
                acc1[1][j] = f2fma(w11, hv.y, acc1[1][j]);
            }
        }
        __syncthreads();  // reads of offsets region done before m1_s overwrite
#pragma unroll
        for (int j = 0; j < JPT; j++) {
            int p = slot * JPT + j;
            float2 v0 = unpk(acc1[0][j]);
            float2 v1 = unpk(acc1[1][j]);
            m1_s[p * 256 + n]       = make_float2(fmaxf(v0.x, 0.f), fmaxf(v0.y, 0.f));
            m1_s[p * 256 + n + 128] = make_float2(fmaxf(v1.x, 0.f), fmaxf(v1.y, 0.f));
        }
    }
    __syncthreads();

    // ---- MLP layer 2 + concat(z) -> dh written into bufs[par]; reset c ----
    {
        float2* hwr = bufs[par];
        if (n < 112) {
            ull acc2[JPT];
            float bb2 = bm2[n];
#pragma unroll
            for (int j = 0; j < JPT; j++) acc2[j] = pk(bb2, bb2);
            const float2* mp = m1_s + (size_t)slot * JPT * 256;
            for (int kk = 0; kk < 128; kk++) {
                float w0 = g_Wm2T[(2 * kk) * 112 + n];
                float w1 = g_Wm2T[(2 * kk + 1) * 112 + n];
                ull W0 = pk(w0, w0), W1 = pk(w1, w1);
#pragma unroll
                for (int j = 0; j < JPT; j++) {
                    ulonglong2 mv = *(const ulonglong2*)(mp + j * 256 + 2 * kk);
                    acc2[j] = f2fma(W0, mv.x, acc2[j]);
                    acc2[j] = f2fma(W1, mv.y, acc2[j]);
                }
            }
#pragma unroll
            for (int j = 0; j < JPT; j++) {
                int p = slot * JPT + j;
                float2 v = unpk(acc2[j]);
                hwr[p * 128 + n] = make_float2(fmaxf(v.x, 0.f), fmaxf(v.y, 0.f));
            }
        }
        {   // z concat: thread -> (pair, zz)
            int p = tid >> 4, zz = tid & 15;
            if (p < NPAIR) {
                int r0 = b0 + 2 * p, r1 = r0 + 1;
                float z0 = (r0 < B) ? z[(size_t)r0 * 16 + zz] : 0.f;
                float z1 = (r1 < B) ? z[(size_t)r1 * 16 + zz] : 0.f;
                hwr[p * 128 + 112 + zz] = make_float2(z0, z1);
            }
        }
        for (int i = tid; i < NPAIR * 128; i += 512) c_s[i] = make_float2(0.f, 0.f);
    }
    __syncthreads();

    // ---- decoder ----
    const int wwid = tid >> 5, lid = tid & 31;
    const int row_l = 4 * wwid + (lid >> 3);          // 0..63
    const bool row_ok = (row_l < ROWS);
    const int row_c = row_ok ? row_l : 0;
    const int kb = lid & 7;
    const bool rlead = row_ok && ((lid & 7) == 0);
    float2 mybase = base_s[row_c];
    float2 oacc = make_float2(0.f, 0.f);
    float br0 = br[0], br1 = br[1];

    for (int s = 0; s < S; s++) {
        lstm_step(bufs[par], bufs[par ^ 1], c_s, ab_s, g_wsD, wstage,
                  (const ull*)offc, (const ull*)(offc + ROWS), n, slot, tid);
        __syncthreads();
        // readout: off = Wr @ h_new + br ; cumsum output
        const float* hv2 = (const float*)bufs[par ^ 1];
        float p0 = 0.f, p1 = 0.f;
        int bidx = (row_c >> 1) * 256 + (row_c & 1);
#pragma unroll 4
        for (int m = 0; m < 16; m++) {
            int k = kb + 8 * m;
            float hvv = hv2[bidx + 2 * k];
            p0 += wr_s[k] * hvv;
            p1 += wr_s[128 + k] * hvv;
        }
        p0 += __shfl_xor_sync(0xffffffffu, p0, 1);
        p0 += __shfl_xor_sync(0xffffffffu, p0, 2);
        p0 += __shfl_xor_sync(0xffffffffu, p0, 4);
        p1 += __shfl_xor_sync(0xffffffffu, p1, 1);
        p1 += __shfl_xor_sync(0xffffffffu, p1, 2);
        p1 += __shfl_xor_sync(0xffffffffu, p1, 4);
        if (rlead) {
            float ox = p0 + br0, oy = p1 + br1;
            oacc.x += ox; oacc.y += oy;
            offc[row_l] = ox;
            offc[ROWS + row_l] = oy;
            int b = b0 + row_l;
            if (b < B) {
                out[((size_t)b * S + s) * 2 + 0] = mybase.x + oacc.x;
                out[((size_t)b * S + s) * 2 + 1] = mybase.y + oacc.y;
            }
        }
        __syncthreads();
        par ^= 1;
    }
}

// ---------------- launch ------------------------------------------------------
extern "C" void kernel_launch(void* const* d_in, const int* in_sizes, int n_in,
                              void* d_out, int out_size) {
    const float* obs   = (const float*)d_in[0];
    const float* We    = (const float*)d_in[2];
    const float* be    = (const float*)d_in[3];
    const float* Wih_e = (const float*)d_in[4];
    const float* Whh_e = (const float*)d_in[5];
    const float* b_e   = (const float*)d_in[6];
    const float* Wm1   = (const float*)d_in[7];
    const float* bm1   = (const float*)d_in[8];
    const float* Wm2   = (const float*)d_in[9];
    const float* bm2   = (const float*)d_in[10];
    const float* Wd    = (const float*)d_in[11];
    const float* bd    = (const float*)d_in[12];
    const float* Wih_d = (const float*)d_in[13];
    const float* Whh_d = (const float*)d_in[14];
    const float* b_d   = (const float*)d_in[15];
    const float* Wr    = (const float*)d_in[16];
    const float* br    = (const float*)d_in[17];
    const float* z     = (const float*)d_in[18];
    float* out = (float*)d_out;

    int NZ = 16;
    int B = in_sizes[18] / NZ;
    int T = in_sizes[0] / (B * 2);
    int S = out_size / (B * 2);
    int E = in_sizes[2] / 2;

    k_prep<<<256, 256>>>(Wih_e, We, be, b_e, Wih_d, Wd, bd, b_d,
                         Whh_e, Whh_d, Wm1, Wm2, E);

    cudaFuncSetAttribute(k_main, cudaFuncAttributeMaxDynamicSharedMemorySize, SMEM_BYTES);
    int grid = (B + ROWS - 1) / ROWS;
    k_main<<<grid, 512, SMEM_BYTES>>>(obs, bm1, bm2, Wr, br, z, out, B, T, S);
}